// round 16
// baseline (speedup 1.0000x reference)
#include <cuda_runtime.h>
#include <cuda_bf16.h>
#include <math.h>
#include <stdint.h>

#define G   32
#define NN  512
#define EE  8192
#define DD  256
#define KK  2048

typedef __nv_bfloat16 bf16;

#define LD64 72
#define P64_ELEMS (128 * LD64)
#define P64_BYTES (P64_ELEMS * 2)       // 18432 B
#define HG_SMEM (4 * P64_BYTES)         // 73728 B
#define LDQ 136
#define P128_ELEMS (128 * LDQ)
#define P128_BYTES (P128_ELEMS * 2)
#define EL_SMEM (2 * P128_BYTES)
#define LDP 264
#define AM_A_ELEMS (128 * LDP)
#define AM_B_ELEMS (256 * LDP)
#define AM_SMEM ((AM_A_ELEMS + AM_B_ELEMS) * 2 + 16 * 128 * 8)
#define DS_SMEM (NN * 64 * 4)

// ---------------- scratch (device globals) ---------------------------------
__device__ bf16  g_Ab  [(size_t)G * NN * NN];
__device__ bf16  g_Xt  [(size_t)G * DD * NN];
__device__ bf16  g_m   [(size_t)G * NN * DD];
__device__ float g_f1  [(size_t)G * NN * DD];
__device__ bf16  g_hb  [(size_t)G * NN * DD];
__device__ bf16  g_qb  [(size_t)G * NN * DD];
__device__ bf16  g_qe  [(size_t)G * NN * DD];
__device__ bf16  g_cnb [(size_t)KK * DD];
__device__ bf16  g_W1t [DD * DD];
__device__ bf16  g_W2t [DD * DD];
__device__ bf16  g_D1t [DD * DD];
__device__ int   g_idx [G * NN];
__device__ float g_epos[G];
__device__ float g_eneg[G];
__device__ float g_ecnt[G];
__device__ float g_vqacc;

// ---------------- cp.async helpers -----------------------------------------
__device__ __forceinline__ void cpasync16(void* smem, const void* gptr) {
    uint32_t a = (uint32_t)__cvta_generic_to_shared(smem);
    asm volatile("cp.async.cg.shared.global [%0], [%1], 16;\n" :: "r"(a), "l"(gptr));
}
#define CP_COMMIT() asm volatile("cp.async.commit_group;\n" ::: "memory")
#define CP_WAIT0()  asm volatile("cp.async.wait_group 0;\n" ::: "memory")

__device__ __forceinline__ void stage64(const bf16* __restrict__ src, size_t ld,
                                        bf16* __restrict__ dstS) {
    int t = threadIdx.x;
#pragma unroll
    for (int i = 0; i < 4; i++) {
        int idx = t + i * 256;
        int r = idx >> 3;
        int c = (idx & 7) * 8;
        cpasync16(&dstS[r * LD64 + c], &src[(size_t)r * ld + c]);
    }
}
__device__ __forceinline__ void stage128(const bf16* __restrict__ src, size_t ld,
                                         bf16* __restrict__ dstS) {
    int t = threadIdx.x;
#pragma unroll
    for (int i = 0; i < 8; i++) {
        int idx = t + i * 256;
        int r = idx >> 4;
        int c = (idx & 15) * 8;
        cpasync16(&dstS[r * LDQ + c], &src[(size_t)r * ld + c]);
    }
}
// rows x 256 cols into pitch LDP; rows staged = 8 * iters (256 threads)
__device__ __forceinline__ void stageP(const bf16* __restrict__ src, size_t ld,
                                       bf16* __restrict__ dstS, int iters) {
    int t = threadIdx.x;
    for (int i = 0; i < iters; i++) {
        int idx = t + i * 256;
        int r = idx >> 5;
        int c = (idx & 31) * 8;
        cpasync16(&dstS[r * LDP + c], &src[(size_t)r * ld + c]);
    }
}

// ---------------- MMA core (ldmatrix + mma.sync) ----------------------------
__device__ __forceinline__ void mma16816(float c[4], uint32_t a0, uint32_t a1,
                                         uint32_t a2, uint32_t a3,
                                         uint32_t b0, uint32_t b1) {
    asm volatile(
        "mma.sync.aligned.m16n8k16.row.col.f32.bf16.bf16.f32 "
        "{%0,%1,%2,%3}, {%4,%5,%6,%7}, {%8,%9}, {%0,%1,%2,%3};\n"
        : "+f"(c[0]), "+f"(c[1]), "+f"(c[2]), "+f"(c[3])
        : "r"(a0), "r"(a1), "r"(a2), "r"(a3), "r"(b0), "r"(b1));
}
__device__ __forceinline__ void ldsm_x4(uint32_t r[4], uint32_t addr) {
    asm volatile("ldmatrix.sync.aligned.m8n8.x4.shared.b16 {%0,%1,%2,%3}, [%4];"
        : "=r"(r[0]), "=r"(r[1]), "=r"(r[2]), "=r"(r[3]) : "r"(addr));
}

// warp tile m64 x n32 (hgemm / edge)
template <int LDPITCH, int KW>
__device__ __forceinline__ void mma_panel(const bf16* As, const bf16* Bs,
                                          int moff, int noff, int lane,
                                          float acc[4][4][4]) {
    uint32_t abase = (uint32_t)__cvta_generic_to_shared(As)
        + (uint32_t)(((moff + (lane & 15)) * LDPITCH + (lane >> 4) * 8) * 2);
    uint32_t bbase = (uint32_t)__cvta_generic_to_shared(Bs)
        + (uint32_t)(((noff + ((lane >> 4) & 1) * 8 + (lane & 7)) * LDPITCH
                      + ((lane >> 3) & 1) * 8) * 2);
#pragma unroll
    for (int kt = 0; kt < KW; kt += 16) {
        uint32_t bfr[2][4];
        ldsm_x4(bfr[0], bbase + kt * 2);
        ldsm_x4(bfr[1], bbase + (16 * LDPITCH + kt) * 2);
#pragma unroll
        for (int fm = 0; fm < 4; fm++) {
            uint32_t a[4];
            ldsm_x4(a, abase + (fm * 16 * LDPITCH + kt) * 2);
#pragma unroll
            for (int fn = 0; fn < 4; fn++)
                mma16816(acc[fm][fn], a[0], a[1], a[2], a[3],
                         bfr[fn >> 1][(fn & 1) * 2], bfr[fn >> 1][(fn & 1) * 2 + 1]);
        }
    }
}

// warp tile m64 x n64 (argmax)
template <int LDPITCH>
__device__ __forceinline__ void mma_panel64(const bf16* As, const bf16* Bs,
                                            int moff, int noff, int lane,
                                            float acc[4][8][4]) {
    uint32_t abase = (uint32_t)__cvta_generic_to_shared(As)
        + (uint32_t)(((moff + (lane & 15)) * LDPITCH + (lane >> 4) * 8) * 2);
    uint32_t bbase = (uint32_t)__cvta_generic_to_shared(Bs)
        + (uint32_t)(((noff + ((lane >> 4) & 1) * 8 + (lane & 7)) * LDPITCH
                      + ((lane >> 3) & 1) * 8) * 2);
#pragma unroll
    for (int kt = 0; kt < 256; kt += 16) {
        uint32_t bfr[4][4];
#pragma unroll
        for (int j = 0; j < 4; j++)
            ldsm_x4(bfr[j], bbase + (j * 16 * LDPITCH + kt) * 2);
#pragma unroll
        for (int fm = 0; fm < 4; fm++) {
            uint32_t a[4];
            ldsm_x4(a, abase + (fm * 16 * LDPITCH + kt) * 2);
#pragma unroll
            for (int fn = 0; fn < 8; fn++)
                mma16816(acc[fm][fn], a[0], a[1], a[2], a[3],
                         bfr[fn >> 1][(fn & 1) * 2], bfr[fn >> 1][(fn & 1) * 2 + 1]);
        }
    }
}

// ---------------- build A: degrees + smem-accumulated scatter ---------------
// reads only harness inputs; trailing gridsync keeps the PDL chain transitive.
__global__ __launch_bounds__(512) void build_A_kernel(const int* __restrict__ src,
                                                      const int* __restrict__ dst) {
    extern __shared__ float accA[];
    __shared__ int co[NN], ci[NN];
    __shared__ float rso[NN], rsi[NN];
    int g = blockIdx.x >> 3;
    int part = blockIdx.x & 7;
    int ss0 = part * 64;
    int t = threadIdx.x;
    for (int i = t; i < NN; i += 512) { co[i] = 0; ci[i] = 0; }
    for (int i = t; i < NN * 64; i += 512) accA[i] = 0.f;
    __syncthreads();
    const int* s = src + g * EE;
    const int* d = dst + g * EE;
    for (int e = t; e < EE; e += 512) {
        atomicAdd(&co[s[e]], 1);
        atomicAdd(&ci[d[e]], 1);
    }
    __syncthreads();
    for (int i = t; i < NN; i += 512) {
        rso[i] = rsqrtf((float)max(co[i], 1));
        rsi[i] = rsqrtf((float)max(ci[i], 1));
    }
    __syncthreads();
    for (int e = t; e < EE; e += 512) {
        int ss = s[e];
        if (ss >= ss0 && ss < ss0 + 64) {
            int dd = d[e];
            atomicAdd(&accA[dd * 64 + (ss - ss0)], rsi[dd] * rso[ss]);
        }
    }
    __syncthreads();
    bf16* A = g_Ab + (size_t)g * NN * NN + ss0;
    for (int i = t; i < NN * 8; i += 512) {
        int r = i >> 3, c8 = (i & 7) * 8;
        const float* v = &accA[r * 64 + c8];
        __nv_bfloat162 p0 = __floats2bfloat162_rn(v[0], v[1]);
        __nv_bfloat162 p1 = __floats2bfloat162_rn(v[2], v[3]);
        __nv_bfloat162 p2 = __floats2bfloat162_rn(v[4], v[5]);
        __nv_bfloat162 p3 = __floats2bfloat162_rn(v[6], v[7]);
        uint4 pk = make_uint4(*(uint32_t*)&p0, *(uint32_t*)&p1,
                              *(uint32_t*)&p2, *(uint32_t*)&p3);
        *(uint4*)(A + (size_t)r * NN + c8) = pk;
    }
    cudaGridDependencySynchronize();
}

// ---------------- prep: codebook norm + weight transposes + acc zero --------
__global__ __launch_bounds__(256) void prep_kernel(const float* __restrict__ cb,
                                                   const float* __restrict__ W1,
                                                   const float* __restrict__ W2,
                                                   const float* __restrict__ D1) {
    __shared__ float tile[32][33];
    int b = blockIdx.x;
    if (b == 0 && threadIdx.x < G) {
        g_epos[threadIdx.x] = 0.f;
        g_eneg[threadIdx.x] = 0.f;
        g_ecnt[threadIdx.x] = 0.f;
        if (threadIdx.x == 0) g_vqacc = 0.f;
    }
    if (b < KK) {
        int k = b;
        float v = cb[(size_t)k * DD + threadIdx.x];
        float ss = v * v;
        __shared__ float red[8];
        for (int o = 16; o > 0; o >>= 1) ss += __shfl_down_sync(0xffffffffu, ss, o);
        if ((threadIdx.x & 31) == 0) red[threadIdx.x >> 5] = ss;
        __syncthreads();
        if (threadIdx.x == 0) {
            float t = 0.f;
            for (int i = 0; i < 8; i++) t += red[i];
            red[0] = t;
        }
        __syncthreads();
        float r = rsqrtf(red[0] + 1e-12f);
        g_cnb[(size_t)k * DD + threadIdx.x] = __float2bfloat16(v * r);
    } else {
        int r2 = b - KK;
        int which = r2 >> 6, t2 = r2 & 63;
        const float* srcW = which == 0 ? W1 : which == 1 ? W2 : D1;
        bf16* dstW = which == 0 ? g_W1t : which == 1 ? g_W2t : g_D1t;
        int bx = t2 & 7, by = t2 >> 3;
        int r0 = by * 32, c0 = bx * 32;
        int tx = threadIdx.x & 31, ty = threadIdx.x >> 5;
#pragma unroll
        for (int i = 0; i < 4; i++) {
            int r = ty + i * 8;
            tile[r][tx] = srcW[(size_t)(r0 + r) * DD + c0 + tx];
        }
        __syncthreads();
#pragma unroll
        for (int i = 0; i < 4; i++) {
            int r = ty + i * 8;
            dstW[(size_t)(c0 + r) * DD + r0 + tx] = __float2bfloat16(tile[tx][r]);
        }
    }
}

// ---------------- transpose + convert (feats) -------------------------------
// reads only harness inputs; trailing gridsync for chain transitivity.
__global__ __launch_bounds__(256) void transpose_kernel(
    const float* __restrict__ in, bf16* __restrict__ out,
    int R, int C, size_t sIn, size_t sOut)
{
    __shared__ float tile[32][33];
    int b = blockIdx.z;
    in  += (size_t)b * sIn;
    out += (size_t)b * sOut;
    int r0 = blockIdx.y * 32, c0 = blockIdx.x * 32;
    int tx = threadIdx.x & 31, ty = threadIdx.x >> 5;
#pragma unroll
    for (int i = 0; i < 4; i++) {
        int r = ty + i * 8;
        tile[r][tx] = in[(size_t)(r0 + r) * C + c0 + tx];
    }
    __syncthreads();
#pragma unroll
    for (int i = 0; i < 4; i++) {
        int r = ty + i * 8;
        out[(size_t)(c0 + r) * R + r0 + tx] = __float2bfloat16(tile[tx][r]);
    }
    cudaGridDependencySynchronize();
}

// ---------------- hgemm (128x128 tile, m64n32 warps, K=64 pipeline) ---------
__global__ __launch_bounds__(256) void hgemm_kernel(
    const bf16* __restrict__ A, const bf16* __restrict__ Bt,
    const float* __restrict__ bias, float* __restrict__ Cf, bf16* __restrict__ Cb,
    int M, int Ncol, int Kd, size_t sA, size_t sBt, size_t sC, int relu)
{
    extern __shared__ bf16 dynsm[];
    bf16* Abuf[2] = { dynsm, dynsm + 2 * P64_ELEMS };
    bf16* Bbuf[2] = { dynsm + P64_ELEMS, dynsm + 3 * P64_ELEMS };
    int b = blockIdx.z;
    A  += (size_t)b * sA;
    Bt += (size_t)b * sBt;
    int rowbase = blockIdx.y * 128, colbase = blockIdx.x * 128;
    int t = threadIdx.x, lane = t & 31, wid = t >> 5;
    int lr = lane >> 2, lq = lane & 3;
    int moff = (wid & 1) * 64, noff = (wid >> 1) * 32;

    cudaGridDependencySynchronize();    // inputs produced by previous kernel

    int P = Kd / 64;
    stage64(A  + (size_t)rowbase * Kd, Kd, Abuf[0]);
    stage64(Bt + (size_t)colbase * Kd, Kd, Bbuf[0]);
    CP_COMMIT();

    float acc[4][4][4] = {};
    for (int p = 0; p < P; p++) {
        CP_WAIT0();
        __syncthreads();
        if (p + 1 < P) {
            stage64(A  + (size_t)rowbase * Kd + (p + 1) * 64, Kd, Abuf[(p + 1) & 1]);
            stage64(Bt + (size_t)colbase * Kd + (p + 1) * 64, Kd, Bbuf[(p + 1) & 1]);
            CP_COMMIT();
        }
        mma_panel<LD64, 64>(Abuf[p & 1], Bbuf[p & 1], moff, noff, lane, acc);
    }
#pragma unroll
    for (int fm = 0; fm < 4; fm++)
#pragma unroll
        for (int fn = 0; fn < 4; fn++)
#pragma unroll
            for (int i = 0; i < 4; i++) {
                int row = rowbase + moff + fm * 16 + lr + (i >> 1) * 8;
                int col = colbase + noff + fn * 8 + 2 * lq + (i & 1);
                float v = acc[fm][fn][i];
                if (bias) v += bias[col];
                if (relu) v = fmaxf(v, 0.f);
                size_t o = (size_t)b * sC + (size_t)row * Ncol + col;
                if (Cf) Cf[o] = v;
                if (Cb) Cb[o] = __float2bfloat16(v);
            }
}

// ---------------- fused layernorm + transpose -------------------------------
__global__ __launch_bounds__(256) void ln_transpose_kernel(
    const float* __restrict__ x, const float* __restrict__ gamma,
    const float* __restrict__ beta, bf16* __restrict__ xt)
{
    __shared__ bf16 tile[32][258];
    __shared__ float gsh[DD], bsh[DD];
    int g = blockIdx.x >> 4;
    int rb = (blockIdx.x & 15) * 32;
    int t = threadIdx.x, lane = t & 31, warp = t >> 5;
    gsh[t] = gamma[t];
    bsh[t] = beta[t];
    cudaGridDependencySynchronize();    // x produced by fc1
    __syncthreads();
#pragma unroll
    for (int rr = 0; rr < 4; rr++) {
        int row = rb + warp * 4 + rr;
        const float* xr = x + ((size_t)g * NN + row) * DD;
        float v[8];
        float s = 0.f;
#pragma unroll
        for (int j = 0; j < 8; j++) { v[j] = xr[lane + j * 32]; s += v[j]; }
        for (int o = 16; o > 0; o >>= 1) s += __shfl_xor_sync(0xffffffffu, s, o);
        float mu = s / DD;
        float s2 = 0.f;
#pragma unroll
        for (int j = 0; j < 8; j++) { float d = v[j] - mu; s2 += d * d; }
        for (int o = 16; o > 0; o >>= 1) s2 += __shfl_xor_sync(0xffffffffu, s2, o);
        float rs = rsqrtf(s2 / DD + 1e-5f);
#pragma unroll
        for (int j = 0; j < 8; j++) {
            int d = lane + j * 32;
            tile[row - rb][d] = __float2bfloat16((v[j] - mu) * rs * gsh[d] + bsh[d]);
        }
    }
    __syncthreads();
    bf16* dst = xt + (size_t)g * DD * NN;
    for (int i = t; i < 32 * DD; i += 256) {
        int d = i >> 5, node = i & 31;
        dst[(size_t)d * NN + rb + node] = tile[node][d];
    }
}

// ---------------- fused VQ argmax: m64n64 warps, 256-code chunks ------------
__global__ __launch_bounds__(256, 1) void argmax_vq_kernel(
    const bf16* __restrict__ hfb, const float* __restrict__ hf,
    const float* __restrict__ cb)
{
    extern __shared__ char smraw[];
    bf16*  As   = (bf16*)smraw;
    bf16*  Bs   = As + AM_A_ELEMS;
    float* redv = (float*)(Bs + AM_B_ELEMS);
    int*   redi = (int*)(redv + 16 * 128);
    int rowbase = blockIdx.x * 128;
    int t = threadIdx.x, lane = t & 31, wid = t >> 5;
    int lr = lane >> 2, lq = lane & 3;
    int moff = (wid & 1) * 64;
    int noff = (wid >> 1) * 64;

    cudaGridDependencySynchronize();    // hfb/hf produced by fc2

    stageP(hfb + (size_t)rowbase * DD, DD, As, 16);
    CP_COMMIT();

    float best[4][2];
    int   bidx[4][2];
#pragma unroll
    for (int fm = 0; fm < 4; fm++)
#pragma unroll
        for (int h = 0; h < 2; h++) { best[fm][h] = -1e30f; bidx[fm][h] = 0; }

    for (int cc = 0; cc < KK / 256; cc++) {
        stageP(g_cnb + (size_t)cc * 256 * DD, DD, Bs, 32);
        CP_COMMIT();
        CP_WAIT0();
        __syncthreads();
        float acc[4][8][4] = {};
        mma_panel64<LDP>(As, Bs, moff, noff, lane, acc);
#pragma unroll
        for (int fm = 0; fm < 4; fm++)
#pragma unroll
            for (int fn = 0; fn < 8; fn++) {
                int colb = cc * 256 + noff + fn * 8 + 2 * lq;
                float* c = acc[fm][fn];
                if (c[0] > best[fm][0]) { best[fm][0] = c[0]; bidx[fm][0] = colb; }
                if (c[1] > best[fm][0]) { best[fm][0] = c[1]; bidx[fm][0] = colb + 1; }
                if (c[2] > best[fm][1]) { best[fm][1] = c[2]; bidx[fm][1] = colb; }
                if (c[3] > best[fm][1]) { best[fm][1] = c[3]; bidx[fm][1] = colb + 1; }
            }
        __syncthreads();
    }
    int owner = (wid >> 1) * 4 + lq;
#pragma unroll
    for (int fm = 0; fm < 4; fm++)
#pragma unroll
        for (int h = 0; h < 2; h++) {
            int lrow = moff + fm * 16 + lr + h * 8;
            redv[owner * 128 + lrow] = best[fm][h];
            redi[owner * 128 + lrow] = bidx[fm][h];
        }
    __syncthreads();
    if (t < 128) {
        float bv = redv[t];
        int bi = redi[t];
        for (int x = 1; x < 16; x++) {
            float v = redv[x * 128 + t];
            int ii = redi[x * 128 + t];
            if (v > bv || (v == bv && ii < bi)) { bv = v; bi = ii; }
        }
        g_idx[rowbase + t] = bi;
        redi[t] = bi;
    }
    __syncthreads();
    {
        int r = t >> 1, half = t & 1;
        int idx = redi[r];
        const float* crow = cb + (size_t)idx * DD + half * 128;
        const float* hrow = hf + (size_t)(rowbase + r) * DD + half * 128;
        bf16* qrow = g_qb + (size_t)(rowbase + r) * DD + half * 128;
        float s = 0.f;
        for (int d = 0; d < 128; d++) {
            float cv = crow[d];
            float df = cv - hrow[d];
            s += df * df;
            qrow[d] = __float2bfloat16(cv);
        }
        for (int o = 16; o > 0; o >>= 1) s += __shfl_down_sync(0xffffffffu, s, o);
        if ((t & 31) == 0) atomicAdd(&g_vqacc, s);
    }
}

// ---------------- fused edge loss -------------------------------------------
__global__ __launch_bounds__(256) void edge_loss_kernel(const bf16* __restrict__ qe) {
    extern __shared__ bf16 dynsm[];
    bf16* As = dynsm;
    bf16* Bs = dynsm + P128_ELEMS;
    __shared__ float redp[8], redn[8], redc[8];
    int g = blockIdx.y;
    int tlin = blockIdx.x;
    int bi = 0, rem = tlin;
    while (rem >= 4 - bi) { rem -= 4 - bi; bi++; }
    int bj = bi + rem;
    const bf16* Q = qe + (size_t)g * NN * DD;
    const unsigned short* AbT = (const unsigned short*)(g_Ab + (size_t)g * NN * NN);

    int t = threadIdx.x, lane = t & 31, wid = t >> 5;
    int lr = lane >> 2, lq = lane & 3;
    int moff = (wid & 1) * 64, noff = (wid >> 1) * 32;
    int rowbase = bi * 128, colbase = bj * 128;

    cudaGridDependencySynchronize();    // qe produced by decoder GEMM

    stage128(Q + (size_t)rowbase * DD, DD, As);
    stage128(Q + (size_t)colbase * DD, DD, Bs);
    CP_COMMIT();
    CP_WAIT0();
    __syncthreads();
    float acc[4][4][4] = {};
    mma_panel<LDQ, 128>(As, Bs, moff, noff, lane, acc);
    __syncthreads();
    stage128(Q + (size_t)rowbase * DD + 128, DD, As);
    stage128(Q + (size_t)colbase * DD + 128, DD, Bs);
    CP_COMMIT();
    CP_WAIT0();
    __syncthreads();
    mma_panel<LDQ, 128>(As, Bs, moff, noff, lane, acc);

    float spos = 0.f, sneg = 0.f, cnt = 0.f;
#pragma unroll
    for (int fm = 0; fm < 4; fm++)
#pragma unroll
        for (int fn = 0; fn < 4; fn++)
#pragma unroll
            for (int i = 0; i < 4; i++) {
                int row = rowbase + moff + fm * 16 + lr + (i >> 1) * 8;
                int col = colbase + noff + fn * 8 + 2 * lq + (i & 1);
                if (row < col) {
                    float x = acc[fm][fn][i];
                    float l1 = log1pf(__expf(-fabsf(x)));
                    float sp_p = fmaxf(x, 0.f) + l1;
                    float sp_n = fmaxf(-x, 0.f) + l1;
                    if (AbT[col * NN + row] != 0) { spos += sp_n; cnt += 1.f; }
                    else                          { sneg += sp_p; }
                }
            }
    for (int o = 16; o > 0; o >>= 1) {
        spos += __shfl_down_sync(0xffffffffu, spos, o);
        sneg += __shfl_down_sync(0xffffffffu, sneg, o);
        cnt  += __shfl_down_sync(0xffffffffu, cnt, o);
    }
    if ((t & 31) == 0) { redp[t >> 5] = spos; redn[t >> 5] = sneg; redc[t >> 5] = cnt; }
    __syncthreads();
    if (t == 0) {
        float tp = 0.f, tn = 0.f, tc = 0.f;
        for (int i = 0; i < 8; i++) { tp += redp[i]; tn += redn[i]; tc += redc[i]; }
        atomicAdd(&g_epos[g], tp);
        atomicAdd(&g_eneg[g], tn);
        atomicAdd(&g_ecnt[g], tc);
    }
}

// ---------------- finalize --------------------------------------------------
__global__ void finalize_kernel(float* out, int out_size) {
    cudaGridDependencySynchronize();
    float es = 0.f;
    for (int g = 0; g < G; g++) {
        float ne = g_ecnt[g];
        float pw = ((float)NN * NN * 0.5f - ne) / (ne + 1e-6f);
        es += (pw * g_epos[g] + g_eneg[g]) / ((float)NN * (NN - 1) * 0.5f);
    }
    es /= (float)G;
    float vq = 1000.0f * g_vqacc / ((float)G * NN * DD);
    float loss = es * 100.0f + vq;
    for (int i = 0; i < out_size; i++) out[i] = loss;
}

// ---------------- launch ----------------------------------------------------
extern "C" void kernel_launch(void* const* d_in, const int* in_sizes, int n_in,
                              void* d_out, int out_size) {
    (void)in_sizes; (void)n_in;
    const float* feats = (const float*)d_in[0];
    const int*   src   = (const int*)  d_in[1];
    const int*   dst   = (const int*)  d_in[2];
    const float* W1    = (const float*)d_in[3];
    const float* b1    = (const float*)d_in[4];
    const float* W2    = (const float*)d_in[5];
    const float* b2    = (const float*)d_in[6];
    const float* gamma = (const float*)d_in[7];
    const float* beta  = (const float*)d_in[8];
    const float* dec1W = (const float*)d_in[9];
    const float* dec1b = (const float*)d_in[10];
    const float* cb    = (const float*)d_in[13];
    float* out = (float*)d_out;

    float* pF1;
    bf16 *pAb, *pXt, *pM, *pHb, *pQb, *pQe, *pW1t, *pW2t, *pD1t;
    cudaGetSymbolAddress((void**)&pF1,  g_f1);
    cudaGetSymbolAddress((void**)&pAb,  g_Ab);
    cudaGetSymbolAddress((void**)&pXt,  g_Xt);
    cudaGetSymbolAddress((void**)&pM,   g_m);
    cudaGetSymbolAddress((void**)&pHb,  g_hb);
    cudaGetSymbolAddress((void**)&pQb,  g_qb);
    cudaGetSymbolAddress((void**)&pQe,  g_qe);
    cudaGetSymbolAddress((void**)&pW1t, g_W1t);
    cudaGetSymbolAddress((void**)&pW2t, g_W2t);
    cudaGetSymbolAddress((void**)&pD1t, g_D1t);

    cudaFuncSetAttribute(hgemm_kernel,
                         cudaFuncAttributeMaxDynamicSharedMemorySize, HG_SMEM);
    cudaFuncSetAttribute(edge_loss_kernel,
                         cudaFuncAttributeMaxDynamicSharedMemorySize, EL_SMEM);
    cudaFuncSetAttribute(argmax_vq_kernel,
                         cudaFuncAttributeMaxDynamicSharedMemorySize, AM_SMEM);
    cudaFuncSetAttribute(build_A_kernel,
                         cudaFuncAttributeMaxDynamicSharedMemorySize, DS_SMEM);

    cudaLaunchAttribute pdl_attr;
    pdl_attr.id = cudaLaunchAttributeProgrammaticStreamSerialization;
    pdl_attr.val.programmaticStreamSerializationAllowed = 1;
    cudaLaunchConfig_t cfg = {};
    cfg.attrs = &pdl_attr;
    cfg.numAttrs = 1;
    cfg.stream = 0;

    // first kernel: normal launch
    prep_kernel<<<KK + 192, 256>>>(cb, W1, W2, dec1W);

    // feats transpose (inputs only; overlaps prep, gridsyncs at end)
    cfg.gridDim = dim3(DD / 32, NN / 32, G);
    cfg.blockDim = dim3(256);
    cfg.dynamicSmemBytes = 0;
    cudaLaunchKernelEx(&cfg, transpose_kernel,
                       feats, pXt, NN, DD, (size_t)(NN * DD), (size_t)(NN * DD));

    // build A (inputs only; overlaps; gridsyncs at end)
    cfg.gridDim = dim3(G * 8);
    cfg.blockDim = dim3(512);
    cfg.dynamicSmemBytes = DS_SMEM;
    cudaLaunchKernelEx(&cfg, build_A_kernel, src, dst);

    // conv1: m = Ab @ Xt^T  (bf16 out)
    cfg.gridDim = dim3(DD / 128, NN / 128, G);
    cfg.blockDim = dim3(256);
    cfg.dynamicSmemBytes = HG_SMEM;
    cudaLaunchKernelEx(&cfg, hgemm_kernel,
                       (const bf16*)pAb, (const bf16*)pXt, (const float*)nullptr,
                       (float*)nullptr, pM, NN, DD, NN,
                       (size_t)NN * NN, (size_t)DD * NN, (size_t)NN * DD, 0);
    // h1 = relu(m @ W1 + b1)  (fp32 out)
    cfg.gridDim = dim3(DD / 128, (G * NN) / 128, 1);
    cudaLaunchKernelEx(&cfg, hgemm_kernel,
                       (const bf16*)pM, (const bf16*)pW1t, b1,
                       pF1, (bf16*)nullptr, G * NN, DD, DD,
                       (size_t)0, (size_t)0, (size_t)0, 1);
    // fused layernorm + transpose -> Xt
    cfg.gridDim = dim3(G * 16);
    cfg.dynamicSmemBytes = 0;
    cudaLaunchKernelEx(&cfg, ln_transpose_kernel, (const float*)pF1, gamma, beta, pXt);
    // conv2
    cfg.gridDim = dim3(DD / 128, NN / 128, G);
    cfg.dynamicSmemBytes = HG_SMEM;
    cudaLaunchKernelEx(&cfg, hgemm_kernel,
                       (const bf16*)pAb, (const bf16*)pXt, (const float*)nullptr,
                       (float*)nullptr, pM, NN, DD, NN,
                       (size_t)NN * NN, (size_t)DD * NN, (size_t)NN * DD, 0);
    // hf = relu(m2 @ W2 + b2)  (fp32 + bf16 out)
    cfg.gridDim = dim3(DD / 128, (G * NN) / 128, 1);
    cudaLaunchKernelEx(&cfg, hgemm_kernel,
                       (const bf16*)pM, (const bf16*)pW2t, b2,
                       pF1, pHb, G * NN, DD, DD,
                       (size_t)0, (size_t)0, (size_t)0, 1);

    // VQ argmax + gather + vq loss
    cfg.gridDim = dim3((G * NN) / 128);
    cfg.dynamicSmemBytes = AM_SMEM;
    cudaLaunchKernelEx(&cfg, argmax_vq_kernel,
                       (const bf16*)pHb, (const float*)pF1, cb);

    // qe = q @ dec1_W + dec1_b
    cfg.gridDim = dim3(DD / 128, (G * NN) / 128, 1);
    cfg.dynamicSmemBytes = HG_SMEM;
    cudaLaunchKernelEx(&cfg, hgemm_kernel,
                       (const bf16*)pQb, (const bf16*)pD1t, dec1b,
                       (float*)nullptr, pQe, G * NN, DD, DD,
                       (size_t)0, (size_t)0, (size_t)0, 0);

    // fused edge BCE loss
    cfg.gridDim = dim3(10, G);
    cfg.dynamicSmemBytes = EL_SMEM;
    cudaLaunchKernelEx(&cfg, edge_loss_kernel, (const bf16*)pQe);

    // finalize
    cfg.gridDim = dim3(1);
    cfg.blockDim = dim3(1);
    cfg.dynamicSmemBytes = 0;
    cudaLaunchKernelEx(&cfg, finalize_kernel, out, out_size);
}

// round 17
// speedup vs baseline: 1.6696x; 1.6696x over previous
#include <cuda_runtime.h>
#include <cuda_bf16.h>
#include <math.h>
#include <stdint.h>

#define G   32
#define NN  512
#define EE  8192
#define DD  256
#define KK  2048

typedef __nv_bfloat16 bf16;

#define LD64 72
#define P64_ELEMS (128 * LD64)
#define P64_BYTES (P64_ELEMS * 2)       // 18432 B
#define HG_SMEM (4 * P64_BYTES)         // 73728 B
#define LDQ 136
#define P128_ELEMS (128 * LDQ)
#define P128_BYTES (P128_ELEMS * 2)
#define EL_SMEM (2 * P128_BYTES)
#define LDP 264
#define AM_A_ELEMS (128 * LDP)          // hf panel / q panel 128 x 256
#define AM_B_ELEMS (256 * LDP)          // codebook chunk / D1t 256 x 256
#define AM_SMEM ((AM_A_ELEMS + AM_B_ELEMS) * 2 + 16 * 128 * 8)
#define DS_SMEM (NN * 64 * 4)

// ---------------- scratch (device globals) ---------------------------------
__device__ bf16  g_Ab  [(size_t)G * NN * NN];
__device__ bf16  g_Xt  [(size_t)G * DD * NN];
__device__ bf16  g_m   [(size_t)G * NN * DD];
__device__ float g_f1  [(size_t)G * NN * DD];
__device__ bf16  g_hb  [(size_t)G * NN * DD];
__device__ bf16  g_qe  [(size_t)G * NN * DD];
__device__ bf16  g_cnb [(size_t)KK * DD];
__device__ bf16  g_W1t [DD * DD];
__device__ bf16  g_W2t [DD * DD];
__device__ bf16  g_D1t [DD * DD];
__device__ int   g_idx [G * NN];
__device__ float g_epos[G];
__device__ float g_eneg[G];
__device__ float g_ecnt[G];
__device__ float g_vqacc;

// ---------------- cp.async helpers -----------------------------------------
__device__ __forceinline__ void cpasync16(void* smem, const void* gptr) {
    uint32_t a = (uint32_t)__cvta_generic_to_shared(smem);
    asm volatile("cp.async.cg.shared.global [%0], [%1], 16;\n" :: "r"(a), "l"(gptr));
}
#define CP_COMMIT() asm volatile("cp.async.commit_group;\n" ::: "memory")
#define CP_WAIT0()  asm volatile("cp.async.wait_group 0;\n" ::: "memory")

__device__ __forceinline__ void stage64(const bf16* __restrict__ src, size_t ld,
                                        bf16* __restrict__ dstS) {
    int t = threadIdx.x;
#pragma unroll
    for (int i = 0; i < 4; i++) {
        int idx = t + i * 256;
        int r = idx >> 3;
        int c = (idx & 7) * 8;
        cpasync16(&dstS[r * LD64 + c], &src[(size_t)r * ld + c]);
    }
}
__device__ __forceinline__ void stage128(const bf16* __restrict__ src, size_t ld,
                                         bf16* __restrict__ dstS) {
    int t = threadIdx.x;
#pragma unroll
    for (int i = 0; i < 8; i++) {
        int idx = t + i * 256;
        int r = idx >> 4;
        int c = (idx & 15) * 8;
        cpasync16(&dstS[r * LDQ + c], &src[(size_t)r * ld + c]);
    }
}
// rows x 256 cols into pitch LDP; rows staged = 8 * iters (256 threads)
__device__ __forceinline__ void stageP(const bf16* __restrict__ src, size_t ld,
                                       bf16* __restrict__ dstS, int iters) {
    int t = threadIdx.x;
    for (int i = 0; i < iters; i++) {
        int idx = t + i * 256;
        int r = idx >> 5;
        int c = (idx & 31) * 8;
        cpasync16(&dstS[r * LDP + c], &src[(size_t)r * ld + c]);
    }
}

// ---------------- MMA core (ldmatrix + mma.sync) ----------------------------
__device__ __forceinline__ void mma16816(float c[4], uint32_t a0, uint32_t a1,
                                         uint32_t a2, uint32_t a3,
                                         uint32_t b0, uint32_t b1) {
    asm volatile(
        "mma.sync.aligned.m16n8k16.row.col.f32.bf16.bf16.f32 "
        "{%0,%1,%2,%3}, {%4,%5,%6,%7}, {%8,%9}, {%0,%1,%2,%3};\n"
        : "+f"(c[0]), "+f"(c[1]), "+f"(c[2]), "+f"(c[3])
        : "r"(a0), "r"(a1), "r"(a2), "r"(a3), "r"(b0), "r"(b1));
}
__device__ __forceinline__ void ldsm_x4(uint32_t r[4], uint32_t addr) {
    asm volatile("ldmatrix.sync.aligned.m8n8.x4.shared.b16 {%0,%1,%2,%3}, [%4];"
        : "=r"(r[0]), "=r"(r[1]), "=r"(r[2]), "=r"(r[3]) : "r"(addr));
}

// warp tile m64 x n32 (hgemm / edge)
template <int LDPITCH, int KW>
__device__ __forceinline__ void mma_panel(const bf16* As, const bf16* Bs,
                                          int moff, int noff, int lane,
                                          float acc[4][4][4]) {
    uint32_t abase = (uint32_t)__cvta_generic_to_shared(As)
        + (uint32_t)(((moff + (lane & 15)) * LDPITCH + (lane >> 4) * 8) * 2);
    uint32_t bbase = (uint32_t)__cvta_generic_to_shared(Bs)
        + (uint32_t)(((noff + ((lane >> 4) & 1) * 8 + (lane & 7)) * LDPITCH
                      + ((lane >> 3) & 1) * 8) * 2);
#pragma unroll
    for (int kt = 0; kt < KW; kt += 16) {
        uint32_t bfr[2][4];
        ldsm_x4(bfr[0], bbase + kt * 2);
        ldsm_x4(bfr[1], bbase + (16 * LDPITCH + kt) * 2);
#pragma unroll
        for (int fm = 0; fm < 4; fm++) {
            uint32_t a[4];
            ldsm_x4(a, abase + (fm * 16 * LDPITCH + kt) * 2);
#pragma unroll
            for (int fn = 0; fn < 4; fn++)
                mma16816(acc[fm][fn], a[0], a[1], a[2], a[3],
                         bfr[fn >> 1][(fn & 1) * 2], bfr[fn >> 1][(fn & 1) * 2 + 1]);
        }
    }
}

// warp tile m64 x n64 (argmax + fused decoder GEMM)
template <int LDPITCH>
__device__ __forceinline__ void mma_panel64(const bf16* As, const bf16* Bs,
                                            int moff, int noff, int lane,
                                            float acc[4][8][4]) {
    uint32_t abase = (uint32_t)__cvta_generic_to_shared(As)
        + (uint32_t)(((moff + (lane & 15)) * LDPITCH + (lane >> 4) * 8) * 2);
    uint32_t bbase = (uint32_t)__cvta_generic_to_shared(Bs)
        + (uint32_t)(((noff + ((lane >> 4) & 1) * 8 + (lane & 7)) * LDPITCH
                      + ((lane >> 3) & 1) * 8) * 2);
#pragma unroll
    for (int kt = 0; kt < 256; kt += 16) {
        uint32_t bfr[4][4];
#pragma unroll
        for (int j = 0; j < 4; j++)
            ldsm_x4(bfr[j], bbase + (j * 16 * LDPITCH + kt) * 2);
#pragma unroll
        for (int fm = 0; fm < 4; fm++) {
            uint32_t a[4];
            ldsm_x4(a, abase + (fm * 16 * LDPITCH + kt) * 2);
#pragma unroll
            for (int fn = 0; fn < 8; fn++)
                mma16816(acc[fm][fn], a[0], a[1], a[2], a[3],
                         bfr[fn >> 1][(fn & 1) * 2], bfr[fn >> 1][(fn & 1) * 2 + 1]);
        }
    }
}

// ---------------- build A ---------------------------------------------------
__global__ __launch_bounds__(512) void build_A_kernel(const int* __restrict__ src,
                                                      const int* __restrict__ dst) {
    extern __shared__ float accA[];
    __shared__ int co[NN], ci[NN];
    __shared__ float rso[NN], rsi[NN];
    int g = blockIdx.x >> 3;
    int part = blockIdx.x & 7;
    int ss0 = part * 64;
    int t = threadIdx.x;
    for (int i = t; i < NN; i += 512) { co[i] = 0; ci[i] = 0; }
    for (int i = t; i < NN * 64; i += 512) accA[i] = 0.f;
    __syncthreads();
    const int* s = src + g * EE;
    const int* d = dst + g * EE;
    for (int e = t; e < EE; e += 512) {
        atomicAdd(&co[s[e]], 1);
        atomicAdd(&ci[d[e]], 1);
    }
    __syncthreads();
    for (int i = t; i < NN; i += 512) {
        rso[i] = rsqrtf((float)max(co[i], 1));
        rsi[i] = rsqrtf((float)max(ci[i], 1));
    }
    __syncthreads();
    for (int e = t; e < EE; e += 512) {
        int ss = s[e];
        if (ss >= ss0 && ss < ss0 + 64) {
            int dd = d[e];
            atomicAdd(&accA[dd * 64 + (ss - ss0)], rsi[dd] * rso[ss]);
        }
    }
    __syncthreads();
    bf16* A = g_Ab + (size_t)g * NN * NN + ss0;
    for (int i = t; i < NN * 8; i += 512) {
        int r = i >> 3, c8 = (i & 7) * 8;
        const float* v = &accA[r * 64 + c8];
        __nv_bfloat162 p0 = __floats2bfloat162_rn(v[0], v[1]);
        __nv_bfloat162 p1 = __floats2bfloat162_rn(v[2], v[3]);
        __nv_bfloat162 p2 = __floats2bfloat162_rn(v[4], v[5]);
        __nv_bfloat162 p3 = __floats2bfloat162_rn(v[6], v[7]);
        uint4 pk = make_uint4(*(uint32_t*)&p0, *(uint32_t*)&p1,
                              *(uint32_t*)&p2, *(uint32_t*)&p3);
        *(uint4*)(A + (size_t)r * NN + c8) = pk;
    }
}

// ---------------- prep ------------------------------------------------------
__global__ __launch_bounds__(256) void prep_kernel(const float* __restrict__ cb,
                                                   const float* __restrict__ W1,
                                                   const float* __restrict__ W2,
                                                   const float* __restrict__ D1) {
    __shared__ float tile[32][33];
    int b = blockIdx.x;
    if (b == 0 && threadIdx.x < G) {
        g_epos[threadIdx.x] = 0.f;
        g_eneg[threadIdx.x] = 0.f;
        g_ecnt[threadIdx.x] = 0.f;
        if (threadIdx.x == 0) g_vqacc = 0.f;
    }
    if (b < KK) {
        int k = b;
        float v = cb[(size_t)k * DD + threadIdx.x];
        float ss = v * v;
        __shared__ float red[8];
        for (int o = 16; o > 0; o >>= 1) ss += __shfl_down_sync(0xffffffffu, ss, o);
        if ((threadIdx.x & 31) == 0) red[threadIdx.x >> 5] = ss;
        __syncthreads();
        if (threadIdx.x == 0) {
            float t = 0.f;
            for (int i = 0; i < 8; i++) t += red[i];
            red[0] = t;
        }
        __syncthreads();
        float r = rsqrtf(red[0] + 1e-12f);
        g_cnb[(size_t)k * DD + threadIdx.x] = __float2bfloat16(v * r);
    } else {
        int r2 = b - KK;
        int which = r2 >> 6, t2 = r2 & 63;
        const float* srcW = which == 0 ? W1 : which == 1 ? W2 : D1;
        bf16* dstW = which == 0 ? g_W1t : which == 1 ? g_W2t : g_D1t;
        int bx = t2 & 7, by = t2 >> 3;
        int r0 = by * 32, c0 = bx * 32;
        int tx = threadIdx.x & 31, ty = threadIdx.x >> 5;
#pragma unroll
        for (int i = 0; i < 4; i++) {
            int r = ty + i * 8;
            tile[r][tx] = srcW[(size_t)(r0 + r) * DD + c0 + tx];
        }
        __syncthreads();
#pragma unroll
        for (int i = 0; i < 4; i++) {
            int r = ty + i * 8;
            dstW[(size_t)(c0 + r) * DD + r0 + tx] = __float2bfloat16(tile[tx][r]);
        }
    }
}

// ---------------- transpose + convert (feats) -------------------------------
__global__ __launch_bounds__(256) void transpose_kernel(
    const float* __restrict__ in, bf16* __restrict__ out,
    int R, int C, size_t sIn, size_t sOut)
{
    __shared__ float tile[32][33];
    int b = blockIdx.z;
    in  += (size_t)b * sIn;
    out += (size_t)b * sOut;
    int r0 = blockIdx.y * 32, c0 = blockIdx.x * 32;
    int tx = threadIdx.x & 31, ty = threadIdx.x >> 5;
#pragma unroll
    for (int i = 0; i < 4; i++) {
        int r = ty + i * 8;
        tile[r][tx] = in[(size_t)(r0 + r) * C + c0 + tx];
    }
    __syncthreads();
#pragma unroll
    for (int i = 0; i < 4; i++) {
        int r = ty + i * 8;
        out[(size_t)(c0 + r) * R + r0 + tx] = __float2bfloat16(tile[tx][r]);
    }
}

// ---------------- hgemm (128x128 tile, m64n32 warps, K=64 pipeline) ---------
__global__ __launch_bounds__(256) void hgemm_kernel(
    const bf16* __restrict__ A, const bf16* __restrict__ Bt,
    const float* __restrict__ bias, float* __restrict__ Cf, bf16* __restrict__ Cb,
    int M, int Ncol, int Kd, size_t sA, size_t sBt, size_t sC, int relu)
{
    extern __shared__ bf16 dynsm[];
    bf16* Abuf[2] = { dynsm, dynsm + 2 * P64_ELEMS };
    bf16* Bbuf[2] = { dynsm + P64_ELEMS, dynsm + 3 * P64_ELEMS };
    int b = blockIdx.z;
    A  += (size_t)b * sA;
    Bt += (size_t)b * sBt;
    int rowbase = blockIdx.y * 128, colbase = blockIdx.x * 128;
    int t = threadIdx.x, lane = t & 31, wid = t >> 5;
    int lr = lane >> 2, lq = lane & 3;
    int moff = (wid & 1) * 64, noff = (wid >> 1) * 32;

    int P = Kd / 64;
    stage64(A  + (size_t)rowbase * Kd, Kd, Abuf[0]);
    stage64(Bt + (size_t)colbase * Kd, Kd, Bbuf[0]);
    CP_COMMIT();

    float acc[4][4][4] = {};
    for (int p = 0; p < P; p++) {
        CP_WAIT0();
        __syncthreads();
        if (p + 1 < P) {
            stage64(A  + (size_t)rowbase * Kd + (p + 1) * 64, Kd, Abuf[(p + 1) & 1]);
            stage64(Bt + (size_t)colbase * Kd + (p + 1) * 64, Kd, Bbuf[(p + 1) & 1]);
            CP_COMMIT();
        }
        mma_panel<LD64, 64>(Abuf[p & 1], Bbuf[p & 1], moff, noff, lane, acc);
    }
#pragma unroll
    for (int fm = 0; fm < 4; fm++)
#pragma unroll
        for (int fn = 0; fn < 4; fn++)
#pragma unroll
            for (int i = 0; i < 4; i++) {
                int row = rowbase + moff + fm * 16 + lr + (i >> 1) * 8;
                int col = colbase + noff + fn * 8 + 2 * lq + (i & 1);
                float v = acc[fm][fn][i];
                if (bias) v += bias[col];
                if (relu) v = fmaxf(v, 0.f);
                size_t o = (size_t)b * sC + (size_t)row * Ncol + col;
                if (Cf) Cf[o] = v;
                if (Cb) Cb[o] = __float2bfloat16(v);
            }
}

// ---------------- fused layernorm + transpose -------------------------------
__global__ __launch_bounds__(256) void ln_transpose_kernel(
    const float* __restrict__ x, const float* __restrict__ gamma,
    const float* __restrict__ beta, bf16* __restrict__ xt)
{
    __shared__ bf16 tile[32][258];
    __shared__ float gsh[DD], bsh[DD];
    int g = blockIdx.x >> 4;
    int rb = (blockIdx.x & 15) * 32;
    int t = threadIdx.x, lane = t & 31, warp = t >> 5;
    gsh[t] = gamma[t];
    bsh[t] = beta[t];
    __syncthreads();
#pragma unroll
    for (int rr = 0; rr < 4; rr++) {
        int row = rb + warp * 4 + rr;
        const float* xr = x + ((size_t)g * NN + row) * DD;
        float v[8];
        float s = 0.f;
#pragma unroll
        for (int j = 0; j < 8; j++) { v[j] = xr[lane + j * 32]; s += v[j]; }
        for (int o = 16; o > 0; o >>= 1) s += __shfl_xor_sync(0xffffffffu, s, o);
        float mu = s / DD;
        float s2 = 0.f;
#pragma unroll
        for (int j = 0; j < 8; j++) { float d = v[j] - mu; s2 += d * d; }
        for (int o = 16; o > 0; o >>= 1) s2 += __shfl_xor_sync(0xffffffffu, s2, o);
        float rs = rsqrtf(s2 / DD + 1e-5f);
#pragma unroll
        for (int j = 0; j < 8; j++) {
            int d = lane + j * 32;
            tile[row - rb][d] = __float2bfloat16((v[j] - mu) * rs * gsh[d] + bsh[d]);
        }
    }
    __syncthreads();
    bf16* dst = xt + (size_t)g * DD * NN;
    for (int i = t; i < 32 * DD; i += 256) {
        int d = i >> 5, node = i & 31;
        dst[(size_t)d * NN + rb + node] = tile[node][d];
    }
}

// ---------------- fused VQ argmax + gather + vq loss + decoder GEMM ---------
__global__ __launch_bounds__(256, 1) void argmax_vq_kernel(
    const bf16* __restrict__ hfb, const float* __restrict__ hf,
    const float* __restrict__ cb, const float* __restrict__ dec1b)
{
    extern __shared__ char smraw[];
    bf16*  As   = (bf16*)smraw;                   // hf panel, later q panel
    bf16*  Bs   = As + AM_A_ELEMS;                // codebook chunks, later D1t
    float* redv = (float*)(Bs + AM_B_ELEMS);
    int*   redi = (int*)(redv + 16 * 128);
    int rowbase = blockIdx.x * 128;
    int t = threadIdx.x, lane = t & 31, wid = t >> 5;
    int lr = lane >> 2, lq = lane & 3;
    int moff = (wid & 1) * 64;
    int noff = (wid >> 1) * 64;

    stageP(hfb + (size_t)rowbase * DD, DD, As, 16);
    CP_COMMIT();

    float best[4][2];
    int   bidx[4][2];
#pragma unroll
    for (int fm = 0; fm < 4; fm++)
#pragma unroll
        for (int h = 0; h < 2; h++) { best[fm][h] = -1e30f; bidx[fm][h] = 0; }

    for (int cc = 0; cc < KK / 256; cc++) {
        stageP(g_cnb + (size_t)cc * 256 * DD, DD, Bs, 32);
        CP_COMMIT();
        CP_WAIT0();
        __syncthreads();
        float acc[4][8][4] = {};
        mma_panel64<LDP>(As, Bs, moff, noff, lane, acc);
#pragma unroll
        for (int fm = 0; fm < 4; fm++)
#pragma unroll
            for (int fn = 0; fn < 8; fn++) {
                int colb = cc * 256 + noff + fn * 8 + 2 * lq;
                float* c = acc[fm][fn];
                if (c[0] > best[fm][0]) { best[fm][0] = c[0]; bidx[fm][0] = colb; }
                if (c[1] > best[fm][0]) { best[fm][0] = c[1]; bidx[fm][0] = colb + 1; }
                if (c[2] > best[fm][1]) { best[fm][1] = c[2]; bidx[fm][1] = colb; }
                if (c[3] > best[fm][1]) { best[fm][1] = c[3]; bidx[fm][1] = colb + 1; }
            }
        __syncthreads();
    }
    int owner = (wid >> 1) * 4 + lq;
#pragma unroll
    for (int fm = 0; fm < 4; fm++)
#pragma unroll
        for (int h = 0; h < 2; h++) {
            int lrow = moff + fm * 16 + lr + h * 8;
            redv[owner * 128 + lrow] = best[fm][h];
            redi[owner * 128 + lrow] = bidx[fm][h];
        }
    __syncthreads();
    if (t < 128) {
        float bv = redv[t];
        int bi = redi[t];
        for (int x = 1; x < 16; x++) {
            float v = redv[x * 128 + t];
            int ii = redi[x * 128 + t];
            if (v > bv || (v == bv && ii < bi)) { bv = v; bi = ii; }
        }
        g_idx[rowbase + t] = bi;
        redi[t] = bi;
    }
    __syncthreads();
    // prefetch D1t into Bs (overlaps the gather below)
    stageP(g_D1t, DD, Bs, 32);
    CP_COMMIT();
    // gather q into As (overwrites hf panel) + fp32 vq partial
    {
        int r = t >> 1, half = t & 1;
        int idx = redi[r];
        const float* crow = cb + (size_t)idx * DD + half * 128;
        const float* hrow = hf + (size_t)(rowbase + r) * DD + half * 128;
        bf16* qrow = As + (size_t)r * LDP + half * 128;
        float s = 0.f;
        for (int d = 0; d < 128; d++) {
            float cv = crow[d];
            float df = cv - hrow[d];
            s += df * df;
            qrow[d] = __float2bfloat16(cv);
        }
        for (int o = 16; o > 0; o >>= 1) s += __shfl_down_sync(0xffffffffu, s, o);
        if ((t & 31) == 0) atomicAdd(&g_vqacc, s);
    }
    CP_WAIT0();
    __syncthreads();
    // decoder GEMM: qe[128 x 256] = q @ D1t^T + dec1b  (bf16 out)
    {
        float acc[4][8][4] = {};
        mma_panel64<LDP>(As, Bs, moff, noff, lane, acc);
#pragma unroll
        for (int fm = 0; fm < 4; fm++)
#pragma unroll
            for (int fn = 0; fn < 8; fn++)
#pragma unroll
                for (int i = 0; i < 4; i++) {
                    int row = moff + fm * 16 + lr + (i >> 1) * 8;
                    int col = noff + fn * 8 + 2 * lq + (i & 1);
                    float v = acc[fm][fn][i] + dec1b[col];
                    g_qe[(size_t)(rowbase + row) * DD + col] = __float2bfloat16(v);
                }
    }
}

// ---------------- fused edge loss -------------------------------------------
__global__ __launch_bounds__(256) void edge_loss_kernel(const bf16* __restrict__ qe) {
    extern __shared__ bf16 dynsm[];
    bf16* As = dynsm;
    bf16* Bs = dynsm + P128_ELEMS;
    __shared__ float redp[8], redn[8], redc[8];
    int g = blockIdx.y;
    int tlin = blockIdx.x;
    int bi = 0, rem = tlin;
    while (rem >= 4 - bi) { rem -= 4 - bi; bi++; }
    int bj = bi + rem;
    const bf16* Q = qe + (size_t)g * NN * DD;
    const unsigned short* AbT = (const unsigned short*)(g_Ab + (size_t)g * NN * NN);

    int t = threadIdx.x, lane = t & 31, wid = t >> 5;
    int lr = lane >> 2, lq = lane & 3;
    int moff = (wid & 1) * 64, noff = (wid >> 1) * 32;
    int rowbase = bi * 128, colbase = bj * 128;

    stage128(Q + (size_t)rowbase * DD, DD, As);
    stage128(Q + (size_t)colbase * DD, DD, Bs);
    CP_COMMIT();
    CP_WAIT0();
    __syncthreads();
    float acc[4][4][4] = {};
    mma_panel<LDQ, 128>(As, Bs, moff, noff, lane, acc);
    __syncthreads();
    stage128(Q + (size_t)rowbase * DD + 128, DD, As);
    stage128(Q + (size_t)colbase * DD + 128, DD, Bs);
    CP_COMMIT();
    CP_WAIT0();
    __syncthreads();
    mma_panel<LDQ, 128>(As, Bs, moff, noff, lane, acc);

    float spos = 0.f, sneg = 0.f, cnt = 0.f;
#pragma unroll
    for (int fm = 0; fm < 4; fm++)
#pragma unroll
        for (int fn = 0; fn < 4; fn++)
#pragma unroll
            for (int i = 0; i < 4; i++) {
                int row = rowbase + moff + fm * 16 + lr + (i >> 1) * 8;
                int col = colbase + noff + fn * 8 + 2 * lq + (i & 1);
                if (row < col) {
                    float x = acc[fm][fn][i];
                    float l1 = log1pf(__expf(-fabsf(x)));
                    float sp_p = fmaxf(x, 0.f) + l1;
                    float sp_n = fmaxf(-x, 0.f) + l1;
                    if (AbT[col * NN + row] != 0) { spos += sp_n; cnt += 1.f; }
                    else                          { sneg += sp_p; }
                }
            }
    for (int o = 16; o > 0; o >>= 1) {
        spos += __shfl_down_sync(0xffffffffu, spos, o);
        sneg += __shfl_down_sync(0xffffffffu, sneg, o);
        cnt  += __shfl_down_sync(0xffffffffu, cnt, o);
    }
    if ((t & 31) == 0) { redp[t >> 5] = spos; redn[t >> 5] = sneg; redc[t >> 5] = cnt; }
    __syncthreads();
    if (t == 0) {
        float tp = 0.f, tn = 0.f, tc = 0.f;
        for (int i = 0; i < 8; i++) { tp += redp[i]; tn += redn[i]; tc += redc[i]; }
        atomicAdd(&g_epos[g], tp);
        atomicAdd(&g_eneg[g], tn);
        atomicAdd(&g_ecnt[g], tc);
    }
}

// ---------------- finalize --------------------------------------------------
__global__ void finalize_kernel(float* out, int out_size) {
    float es = 0.f;
    for (int g = 0; g < G; g++) {
        float ne = g_ecnt[g];
        float pw = ((float)NN * NN * 0.5f - ne) / (ne + 1e-6f);
        es += (pw * g_epos[g] + g_eneg[g]) / ((float)NN * (NN - 1) * 0.5f);
    }
    es /= (float)G;
    float vq = 1000.0f * g_vqacc / ((float)G * NN * DD);
    float loss = es * 100.0f + vq;
    for (int i = 0; i < out_size; i++) out[i] = loss;
}

// ---------------- launch ----------------------------------------------------
extern "C" void kernel_launch(void* const* d_in, const int* in_sizes, int n_in,
                              void* d_out, int out_size) {
    (void)in_sizes; (void)n_in;
    const float* feats = (const float*)d_in[0];
    const int*   src   = (const int*)  d_in[1];
    const int*   dst   = (const int*)  d_in[2];
    const float* W1    = (const float*)d_in[3];
    const float* b1    = (const float*)d_in[4];
    const float* W2    = (const float*)d_in[5];
    const float* b2    = (const float*)d_in[6];
    const float* gamma = (const float*)d_in[7];
    const float* beta  = (const float*)d_in[8];
    const float* dec1W = (const float*)d_in[9];
    const float* dec1b = (const float*)d_in[10];
    const float* cb    = (const float*)d_in[13];
    float* out = (float*)d_out;

    float* pF1;
    bf16 *pAb, *pXt, *pM, *pHb, *pQe, *pW1t, *pW2t, *pD1t;
    cudaGetSymbolAddress((void**)&pF1,  g_f1);
    cudaGetSymbolAddress((void**)&pAb,  g_Ab);
    cudaGetSymbolAddress((void**)&pXt,  g_Xt);
    cudaGetSymbolAddress((void**)&pM,   g_m);
    cudaGetSymbolAddress((void**)&pHb,  g_hb);
    cudaGetSymbolAddress((void**)&pQe,  g_qe);
    cudaGetSymbolAddress((void**)&pW1t, g_W1t);
    cudaGetSymbolAddress((void**)&pW2t, g_W2t);
    cudaGetSymbolAddress((void**)&pD1t, g_D1t);

    cudaFuncSetAttribute(hgemm_kernel,
                         cudaFuncAttributeMaxDynamicSharedMemorySize, HG_SMEM);
    cudaFuncSetAttribute(edge_loss_kernel,
                         cudaFuncAttributeMaxDynamicSharedMemorySize, EL_SMEM);
    cudaFuncSetAttribute(argmax_vq_kernel,
                         cudaFuncAttributeMaxDynamicSharedMemorySize, AM_SMEM);
    cudaFuncSetAttribute(build_A_kernel,
                         cudaFuncAttributeMaxDynamicSharedMemorySize, DS_SMEM);

    prep_kernel<<<KK + 192, 256>>>(cb, W1, W2, dec1W);
    transpose_kernel<<<dim3(DD / 32, NN / 32, G), 256>>>(
        feats, pXt, NN, DD, (size_t)NN * DD, (size_t)NN * DD);
    build_A_kernel<<<G * 8, 512, DS_SMEM>>>(src, dst);

    // conv1
    hgemm_kernel<<<dim3(DD / 128, NN / 128, G), 256, HG_SMEM>>>(
        pAb, pXt, nullptr, nullptr, pM, NN, DD, NN,
        (size_t)NN * NN, (size_t)DD * NN, (size_t)NN * DD, 0);
    // h1 = relu(m @ W1 + b1)
    hgemm_kernel<<<dim3(DD / 128, (G * NN) / 128, 1), 256, HG_SMEM>>>(
        pM, pW1t, b1, pF1, nullptr, G * NN, DD, DD, 0, 0, 0, 1);
    ln_transpose_kernel<<<G * 16, 256>>>(pF1, gamma, beta, pXt);
    // conv2
    hgemm_kernel<<<dim3(DD / 128, NN / 128, G), 256, HG_SMEM>>>(
        pAb, pXt, nullptr, nullptr, pM, NN, DD, NN,
        (size_t)NN * NN, (size_t)DD * NN, (size_t)NN * DD, 0);
    // hf = relu(m2 @ W2 + b2)
    hgemm_kernel<<<dim3(DD / 128, (G * NN) / 128, 1), 256, HG_SMEM>>>(
        pM, pW2t, b2, pF1, pHb, G * NN, DD, DD, 0, 0, 0, 1);

    // VQ argmax + gather + vq loss + decoder GEMM (writes qe directly)
    argmax_vq_kernel<<<(G * NN) / 128, 256, AM_SMEM>>>(pHb, pF1, cb, dec1b);

    edge_loss_kernel<<<dim3(10, G), 256, EL_SMEM>>>(pQe);

    finalize_kernel<<<1, 1>>>(out, out_size);
}